// round 11
// baseline (speedup 1.0000x reference)
#include <cuda_runtime.h>
#include <cstdint>

#define DIM   768
#define POOL  20
#define TOPK  9
#define NVEC  6                 // float4 chunks per lane: 768/4/32
#define NV8   3                 // float8 chunks per lane: 768/8/32
#define ROWS_PER_BLOCK 16       // 8 warps x 2 rows

// Allocation-free scratch
__device__ float        g_kn[POOL * DIM];
__device__ float        g_rowsum[POOL];
__device__ unsigned int g_count[POOL];
__device__ unsigned int g_done = 0;

// ---------------------------------------------------------------------------
// 256-bit copy: ld.global.nc.v8.f32 -> st.global.cs.v8.f32 (sm_100+)
// ---------------------------------------------------------------------------
__device__ __forceinline__ void copy256_stream(const float* __restrict__ src,
                                               float* __restrict__ dst)
{
    float a, b, c, d, e, f, g, h;
    asm volatile("ld.global.nc.v8.f32 {%0,%1,%2,%3,%4,%5,%6,%7}, [%8];"
                 : "=f"(a), "=f"(b), "=f"(c), "=f"(d),
                   "=f"(e), "=f"(f), "=f"(g), "=f"(h)
                 : "l"(src));
    asm volatile("st.global.cs.v8.f32 [%0], {%1,%2,%3,%4,%5,%6,%7,%8};"
                 :: "l"(dst), "f"(a), "f"(b), "f"(c), "f"(d),
                    "f"(e), "f"(f), "f"(g), "f"(h)
                 : "memory");
}

// ---------------------------------------------------------------------------
// prep: 1 block x 640 threads. Warp w normalizes key row w (shuffle-only).
// ---------------------------------------------------------------------------
__global__ void prep_kernel(const float* __restrict__ keys,
                            const int*   __restrict__ layer)
{
    const int w    = threadIdx.x >> 5;
    const int lane = threadIdx.x & 31;
    if (w < POOL) {
        const float* __restrict__ krow =
            keys + ((size_t)(*layer) * POOL + w) * DIM;
        float ss = 0.f;
        #pragma unroll
        for (int i = 0; i < DIM / 32; i++) {
            float v = __ldg(krow + lane + 32 * i);
            ss += v * v;
        }
        #pragma unroll
        for (int off = 16; off; off >>= 1)
            ss += __shfl_xor_sync(0xffffffffu, ss, off);
        const float inv = 1.f / fmaxf(sqrtf(ss), 1e-12f);
        #pragma unroll
        for (int i = 0; i < DIM / 32; i++)
            g_kn[w * DIM + lane + 32 * i] = __ldg(krow + lane + 32 * i) * inv;
    }
    if (threadIdx.x < POOL) {
        g_count[threadIdx.x]  = 0u;
        g_rowsum[threadIdx.x] = 0.f;
    }
}

// ---------------------------------------------------------------------------
// top-9 on a 20-vector in registers (strict '>' matches lax.top_k ties)
// ---------------------------------------------------------------------------
__device__ __forceinline__ uint64_t topk_pack(float* s)
{
    uint64_t packed = 0;
    #pragma unroll
    for (int t = 0; t < TOPK; t++) {
        float best = -3.4e38f; int bj = 0;
        #pragma unroll
        for (int j = 0; j < POOL; j++)
            if (s[j] > best) { best = s[j]; bj = j; }
        packed |= (uint64_t)bj << (7 * t);
        #pragma unroll
        for (int j = 0; j < POOL; j++)
            if (j == bj) s[j] = -3.4e38f;
    }
    return packed;
}

// ---------------------------------------------------------------------------
// main: one warp per 2 rows (R2 engine), 256-bit gather, fused finalize.
// ---------------------------------------------------------------------------
__global__ void __launch_bounds__(256)
pool_main(const float* __restrict__ x,
          const float* __restrict__ prompts,
          const int*   __restrict__ layer,
          float*       __restrict__ out,
          int B, long long total, long long out_sz)
{
    __shared__ unsigned int s_count[POOL];
    __shared__ unsigned int s_last;
    if (threadIdx.x < POOL) s_count[threadIdx.x] = 0u;
    __syncthreads();

    const int warp = threadIdx.x >> 5;
    const int lane = threadIdx.x & 31;
    const int r0   = blockIdx.x * ROWS_PER_BLOCK + warp * 2;
    const int r1c  = r0 + 1;
    const bool has1 = (r1c < B);
    const int r1   = has1 ? r1c : r0;

    if (r0 < B) {
        const float4* __restrict__ xr0 = (const float4*)(x + (size_t)r0 * DIM);
        const float4* __restrict__ xr1 = (const float4*)(x + (size_t)r1 * DIM);
        const float4* __restrict__ knv = (const float4*)g_kn;

        float s0[POOL], s1[POOL];
        #pragma unroll
        for (int j = 0; j < POOL; j++) { s0[j] = 0.f; s1[j] = 0.f; }
        float ss0 = 0.f, ss1 = 0.f;

        #pragma unroll
        for (int i = 0; i < NVEC; i++) {
            const float4 xv0 = __ldcs(xr0 + lane + 32 * i);
            const float4 xv1 = __ldcs(xr1 + lane + 32 * i);
            ss0 += xv0.x * xv0.x + xv0.y * xv0.y + xv0.z * xv0.z + xv0.w * xv0.w;
            ss1 += xv1.x * xv1.x + xv1.y * xv1.y + xv1.z * xv1.z + xv1.w * xv1.w;
            #pragma unroll
            for (int j = 0; j < POOL; j++) {
                const float4 kv = __ldg(knv + j * (DIM / 4) + lane + 32 * i);
                s0[j] += xv0.x * kv.x + xv0.y * kv.y + xv0.z * kv.z + xv0.w * kv.w;
                s1[j] += xv1.x * kv.x + xv1.y * kv.y + xv1.z * kv.z + xv1.w * kv.w;
            }
        }

        // butterfly reduce all 42 accumulators
        #pragma unroll
        for (int off = 16; off; off >>= 1) {
            ss0 += __shfl_xor_sync(0xffffffffu, ss0, off);
            ss1 += __shfl_xor_sync(0xffffffffu, ss1, off);
            #pragma unroll
            for (int j = 0; j < POOL; j++) {
                s0[j] += __shfl_xor_sync(0xffffffffu, s0[j], off);
                s1[j] += __shfl_xor_sync(0xffffffffu, s1[j], off);
            }
        }

        const float inv0 = 1.f / fmaxf(sqrtf(ss0), 1e-12f);
        const float inv1 = 1.f / fmaxf(sqrtf(ss1), 1e-12f);
        #pragma unroll
        for (int j = 0; j < POOL; j++) { s0[j] *= inv0; s1[j] *= inv1; }

        // dist bookkeeping: pool-sums of sim rows 0..19
        if (lane == 0) {
            if (r0 < POOL) {
                float rs = 0.f;
                #pragma unroll
                for (int j = 0; j < POOL; j++) rs += s0[j];
                g_rowsum[r0] = rs;
            }
            if (has1 && r1 < POOL) {
                float rs = 0.f;
                #pragma unroll
                for (int j = 0; j < POOL; j++) rs += s1[j];
                g_rowsum[r1] = rs;
            }
        }

        const uint64_t p0 = topk_pack(s0);
        const uint64_t p1 = topk_pack(s1);

        if (lane == 0) {
            #pragma unroll
            for (int t = 0; t < TOPK; t++) {
                atomicAdd(&s_count[(int)((p0 >> (7 * t)) & 127)], 1u);
                if (has1)
                    atomicAdd(&s_count[(int)((p1 >> (7 * t)) & 127)], 1u);
            }
        }

        // gather: 18 prompt-row copies via 256-bit ld/st (3 per lane per row)
        const float* __restrict__ pbase =
            prompts + (size_t)(*layer) * POOL * DIM;
        float* __restrict__ o0 = out + (size_t)r0 * (TOPK * DIM);
        float* __restrict__ o1 = out + (size_t)r1 * (TOPK * DIM);
        #pragma unroll
        for (int t = 0; t < TOPK; t++) {
            const float* pr0 = pbase + (int)((p0 >> (7 * t)) & 127) * DIM;
            #pragma unroll
            for (int i = 0; i < NV8; i++) {
                const int off = (i * 32 + lane) * 8;
                copy256_stream(pr0 + off, o0 + t * DIM + off);
            }
        }
        if (has1) {
            #pragma unroll
            for (int t = 0; t < TOPK; t++) {
                const float* pr1 = pbase + (int)((p1 >> (7 * t)) & 127) * DIM;
                #pragma unroll
                for (int i = 0; i < NV8; i++) {
                    const int off = (i * 32 + lane) * 8;
                    copy256_stream(pr1 + off, o1 + t * DIM + off);
                }
            }
        }
    }

    __syncthreads();
    if (threadIdx.x < POOL)
        atomicAdd(&g_count[threadIdx.x], s_count[threadIdx.x]);

    // last-block finalize: dist = 1 - sum_r count[r]*rowsum[r] / (B*9*20)
    __threadfence();
    if (threadIdx.x == 0)
        s_last = (atomicAdd(&g_done, 1u) == gridDim.x - 1) ? 1u : 0u;
    __syncthreads();
    if (s_last && threadIdx.x == 0) {
        double acc = 0.0;
        #pragma unroll
        for (int r = 0; r < POOL; r++)
            acc += (double)g_count[r] * (double)g_rowsum[r];
        const float dist = (float)(1.0 - acc / ((double)B * TOPK * POOL));
        for (long long i = total; i < out_sz; i++) out[i] = dist;
        g_done = 0;   // reset for next graph replay (prep re-zeros the rest)
    }
}

extern "C" void kernel_launch(void* const* d_in, const int* in_sizes, int n_in,
                              void* d_out, int out_size)
{
    const float* x       = (const float*)d_in[0];
    const float* keys    = (const float*)d_in[1];
    const float* prompts = (const float*)d_in[2];
    const int*   layer   = (const int*)d_in[3];

    const int B = in_sizes[0] / DIM;
    const long long total = (long long)B * TOPK * DIM;

    prep_kernel<<<1, 640>>>(keys, layer);
    pool_main<<<(B + ROWS_PER_BLOCK - 1) / ROWS_PER_BLOCK, 256>>>(
        x, prompts, layer, (float*)d_out, B, total, (long long)out_size);
}

// round 12
// speedup vs baseline: 1.2376x; 1.2376x over previous
#include <cuda_runtime.h>
#include <cstdint>

#define DIM   768
#define POOL  20
#define TOPK  9
#define NVEC  6                 // float4 chunks per lane: 768 / 4 / 32
#define WARPS 8
#define ROWS_PER_WARP  2
#define ROWS_PER_BLOCK (WARPS * ROWS_PER_WARP)   // 16

// Allocation-free scratch
__device__ float        g_kn[POOL * DIM];
__device__ float        g_rowsum[POOL];
__device__ unsigned int g_count[POOL];
__device__ unsigned int g_done = 0;

// ---------------------------------------------------------------------------
// prep: 1 block x 640 threads. Warp w normalizes key row w (shuffle-only).
// Also re-zeros the accumulators every replay (graph determinism).
// ---------------------------------------------------------------------------
__global__ void prep_kernel(const float* __restrict__ keys,
                            const int*   __restrict__ layer)
{
    const int w    = threadIdx.x >> 5;
    const int lane = threadIdx.x & 31;

    if (w < POOL) {
        const float* __restrict__ krow =
            keys + ((size_t)(*layer) * POOL + w) * DIM;
        float ss = 0.f;
        #pragma unroll
        for (int i = 0; i < DIM / 32; i++) {
            float v = __ldg(krow + lane + 32 * i);
            ss += v * v;
        }
        #pragma unroll
        for (int off = 16; off; off >>= 1)
            ss += __shfl_xor_sync(0xffffffffu, ss, off);
        const float inv = 1.f / fmaxf(sqrtf(ss), 1e-12f);
        #pragma unroll
        for (int i = 0; i < DIM / 32; i++)
            g_kn[w * DIM + lane + 32 * i] = __ldg(krow + lane + 32 * i) * inv;
    }
    if (threadIdx.x < POOL) {
        g_count[threadIdx.x]  = 0u;
        g_rowsum[threadIdx.x] = 0.f;
    }
}

// ---------------------------------------------------------------------------
// main: one warp handles TWO batch rows (R2 engine, unchanged), plus a
// last-block finalize epilogue that replaces the finalize launch.
// ---------------------------------------------------------------------------
__global__ void __launch_bounds__(256)
pool_main(const float* __restrict__ x,
          const float* __restrict__ prompts,
          const int*   __restrict__ layer,
          float*       __restrict__ out,
          int B, long long total, long long out_sz)
{
    __shared__ unsigned int s_count[POOL];
    __shared__ unsigned int s_last;
    if (threadIdx.x < POOL) s_count[threadIdx.x] = 0u;
    __syncthreads();

    const int warp = threadIdx.x >> 5;
    const int lane = threadIdx.x & 31;
    const int r0   = blockIdx.x * ROWS_PER_BLOCK + warp * ROWS_PER_WARP;
    const int r1   = r0 + 1;

    if (r1 < B) {
        const float4* __restrict__ xr0 = (const float4*)(x + (size_t)r0 * DIM);
        const float4* __restrict__ xr1 = (const float4*)(x + (size_t)r1 * DIM);
        const float4* __restrict__ knv = (const float4*)g_kn;

        float s0[POOL], s1[POOL];
        #pragma unroll
        for (int j = 0; j < POOL; j++) { s0[j] = 0.f; s1[j] = 0.f; }
        float ss0 = 0.f, ss1 = 0.f;

        #pragma unroll
        for (int i = 0; i < NVEC; i++) {
            // streaming loads: evict-first, keep keys/prompts resident in L1
            const float4 xv0 = __ldcs(xr0 + lane + 32 * i);
            const float4 xv1 = __ldcs(xr1 + lane + 32 * i);
            ss0 += xv0.x * xv0.x + xv0.y * xv0.y + xv0.z * xv0.z + xv0.w * xv0.w;
            ss1 += xv1.x * xv1.x + xv1.y * xv1.y + xv1.z * xv1.z + xv1.w * xv1.w;
            #pragma unroll
            for (int j = 0; j < POOL; j++) {
                const float4 kv = __ldg(knv + j * (DIM / 4) + lane + 32 * i);
                s0[j] += xv0.x * kv.x + xv0.y * kv.y + xv0.z * kv.z + xv0.w * kv.w;
                s1[j] += xv1.x * kv.x + xv1.y * kv.y + xv1.z * kv.z + xv1.w * kv.w;
            }
        }

        // butterfly reduce all 42 accumulators
        #pragma unroll
        for (int off = 16; off; off >>= 1) {
            ss0 += __shfl_xor_sync(0xffffffffu, ss0, off);
            ss1 += __shfl_xor_sync(0xffffffffu, ss1, off);
            #pragma unroll
            for (int j = 0; j < POOL; j++) {
                s0[j] += __shfl_xor_sync(0xffffffffu, s0[j], off);
                s1[j] += __shfl_xor_sync(0xffffffffu, s1[j], off);
            }
        }

        const float inv0 = 1.f / fmaxf(sqrtf(ss0), 1e-12f);
        const float inv1 = 1.f / fmaxf(sqrtf(ss1), 1e-12f);
        #pragma unroll
        for (int j = 0; j < POOL; j++) { s0[j] *= inv0; s1[j] *= inv1; }

        // dist bookkeeping: pool-sums of sim rows 0..19
        if (lane == 0) {
            if (r0 < POOL) {
                float rs = 0.f;
                #pragma unroll
                for (int j = 0; j < POOL; j++) rs += s0[j];
                g_rowsum[r0] = rs;
            }
            if (r1 < POOL) {
                float rs = 0.f;
                #pragma unroll
                for (int j = 0; j < POOL; j++) rs += s1[j];
                g_rowsum[r1] = rs;
            }
        }

        // iterative top-9 (strict '>' => lower index wins ties, matches lax.top_k)
        int idx0[TOPK], idx1[TOPK];
        #pragma unroll
        for (int t = 0; t < TOPK; t++) {
            float best = -3.4e38f; int bj = 0;
            #pragma unroll
            for (int j = 0; j < POOL; j++)
                if (s0[j] > best) { best = s0[j]; bj = j; }
            idx0[t] = bj;
            #pragma unroll
            for (int j = 0; j < POOL; j++)
                if (j == bj) s0[j] = -3.4e38f;
        }
        #pragma unroll
        for (int t = 0; t < TOPK; t++) {
            float best = -3.4e38f; int bj = 0;
            #pragma unroll
            for (int j = 0; j < POOL; j++)
                if (s1[j] > best) { best = s1[j]; bj = j; }
            idx1[t] = bj;
            #pragma unroll
            for (int j = 0; j < POOL; j++)
                if (j == bj) s1[j] = -3.4e38f;
        }

        if (lane == 0) {
            #pragma unroll
            for (int t = 0; t < TOPK; t++) {
                atomicAdd(&s_count[idx0[t]], 1u);
                atomicAdd(&s_count[idx1[t]], 1u);
            }
        }

        // gather: 18 prompt-row copies, coalesced streaming stores
        const float4* __restrict__ pbase =
            (const float4*)(prompts + (size_t)(*layer) * POOL * DIM);
        float4* __restrict__ o0 = (float4*)out + (size_t)r0 * (TOPK * DIM / 4);
        float4* __restrict__ o1 = (float4*)out + (size_t)r1 * (TOPK * DIM / 4);
        #pragma unroll
        for (int t = 0; t < TOPK; t++) {
            const float4* pr0 = pbase + idx0[t] * (DIM / 4);
            const float4* pr1 = pbase + idx1[t] * (DIM / 4);
            #pragma unroll
            for (int i = 0; i < NVEC; i++) {
                __stcs(o0 + t * (DIM / 4) + lane + 32 * i, __ldg(pr0 + lane + 32 * i));
                __stcs(o1 + t * (DIM / 4) + lane + 32 * i, __ldg(pr1 + lane + 32 * i));
            }
        }
    }

    __syncthreads();
    if (threadIdx.x < POOL)
        atomicAdd(&g_count[threadIdx.x], s_count[threadIdx.x]);

    // last-block finalize: dist = 1 - sum_r count[r]*rowsum[r] / (B*9*20)
    __threadfence();
    if (threadIdx.x == 0)
        s_last = (atomicAdd(&g_done, 1u) == gridDim.x - 1) ? 1u : 0u;
    __syncthreads();
    if (s_last && threadIdx.x == 0) {
        double acc = 0.0;
        #pragma unroll
        for (int r = 0; r < POOL; r++)
            acc += (double)g_count[r] * (double)g_rowsum[r];
        const float dist = (float)(1.0 - acc / ((double)B * TOPK * POOL));
        for (long long i = total; i < out_sz; i++) out[i] = dist;
        g_done = 0;   // reset for the next graph replay (prep re-zeros the rest)
    }
}

extern "C" void kernel_launch(void* const* d_in, const int* in_sizes, int n_in,
                              void* d_out, int out_size)
{
    const float* x       = (const float*)d_in[0];
    const float* keys    = (const float*)d_in[1];
    const float* prompts = (const float*)d_in[2];
    const int*   layer   = (const int*)d_in[3];

    const int B = in_sizes[0] / DIM;
    const long long total = (long long)B * TOPK * DIM;

    prep_kernel<<<1, 640>>>(keys, layer);
    pool_main<<<(B + ROWS_PER_BLOCK - 1) / ROWS_PER_BLOCK, 256>>>(
        x, prompts, layer, (float*)d_out, B, total, (long long)out_size);
}

// round 13
// speedup vs baseline: 1.3576x; 1.0969x over previous
#include <cuda_runtime.h>

#define DIM   768
#define POOL  20
#define TOPK  9
#define NVEC  6                 // float4 chunks per lane: 768 / 4 / 32
#define WARPS 8
#define ROWS_PER_WARP  2
#define ROWS_PER_BLOCK (WARPS * ROWS_PER_WARP)   // 16

// Allocation-free scratch
__device__ float        g_kn[POOL * DIM];
__device__ float        g_rowsum[POOL];
__device__ unsigned int g_count[POOL];

// ---------------------------------------------------------------------------
// prep: 1 block x 640 threads. Warp w normalizes key row w (shuffle-only).
// Re-zeros accumulators every replay (graph determinism).
// ---------------------------------------------------------------------------
__global__ void prep_kernel(const float* __restrict__ keys,
                            const int*   __restrict__ layer)
{
    const int w    = threadIdx.x >> 5;
    const int lane = threadIdx.x & 31;

    if (w < POOL) {
        const float* __restrict__ krow =
            keys + ((size_t)(*layer) * POOL + w) * DIM;
        float ss = 0.f;
        #pragma unroll
        for (int i = 0; i < DIM / 32; i++) {
            float v = __ldg(krow + lane + 32 * i);
            ss += v * v;
        }
        #pragma unroll
        for (int off = 16; off; off >>= 1)
            ss += __shfl_xor_sync(0xffffffffu, ss, off);
        const float inv = 1.f / fmaxf(sqrtf(ss), 1e-12f);
        #pragma unroll
        for (int i = 0; i < DIM / 32; i++)
            g_kn[w * DIM + lane + 32 * i] = __ldg(krow + lane + 32 * i) * inv;
    }
    if (threadIdx.x < POOL) {
        g_count[threadIdx.x]  = 0u;
        g_rowsum[threadIdx.x] = 0.f;
    }
}

// ---------------------------------------------------------------------------
// main: one warp handles TWO batch rows (R2 engine, unchanged) with a
// register cap that admits a 3rd resident CTA per SM.
// ---------------------------------------------------------------------------
__global__ void __launch_bounds__(256, 3)
pool_main(const float* __restrict__ x,
          const float* __restrict__ prompts,
          const int*   __restrict__ layer,
          float*       __restrict__ out,
          int B)
{
    __shared__ unsigned int s_count[POOL];
    if (threadIdx.x < POOL) s_count[threadIdx.x] = 0u;
    __syncthreads();

    const int warp = threadIdx.x >> 5;
    const int lane = threadIdx.x & 31;
    const int r0   = blockIdx.x * ROWS_PER_BLOCK + warp * ROWS_PER_WARP;
    const int r1   = r0 + 1;

    if (r1 < B) {
        const float4* __restrict__ xr0 = (const float4*)(x + (size_t)r0 * DIM);
        const float4* __restrict__ xr1 = (const float4*)(x + (size_t)r1 * DIM);
        const float4* __restrict__ knv = (const float4*)g_kn;

        float s0[POOL], s1[POOL];
        #pragma unroll
        for (int j = 0; j < POOL; j++) { s0[j] = 0.f; s1[j] = 0.f; }
        float ss0 = 0.f, ss1 = 0.f;

        #pragma unroll
        for (int i = 0; i < NVEC; i++) {
            // streaming loads: evict-first, keep keys/prompts resident in L1
            const float4 xv0 = __ldcs(xr0 + lane + 32 * i);
            const float4 xv1 = __ldcs(xr1 + lane + 32 * i);
            ss0 += xv0.x * xv0.x + xv0.y * xv0.y + xv0.z * xv0.z + xv0.w * xv0.w;
            ss1 += xv1.x * xv1.x + xv1.y * xv1.y + xv1.z * xv1.z + xv1.w * xv1.w;
            #pragma unroll
            for (int j = 0; j < POOL; j++) {
                const float4 kv = __ldg(knv + j * (DIM / 4) + lane + 32 * i);
                s0[j] += xv0.x * kv.x + xv0.y * kv.y + xv0.z * kv.z + xv0.w * kv.w;
                s1[j] += xv1.x * kv.x + xv1.y * kv.y + xv1.z * kv.z + xv1.w * kv.w;
            }
        }

        // butterfly reduce all 42 accumulators
        #pragma unroll
        for (int off = 16; off; off >>= 1) {
            ss0 += __shfl_xor_sync(0xffffffffu, ss0, off);
            ss1 += __shfl_xor_sync(0xffffffffu, ss1, off);
            #pragma unroll
            for (int j = 0; j < POOL; j++) {
                s0[j] += __shfl_xor_sync(0xffffffffu, s0[j], off);
                s1[j] += __shfl_xor_sync(0xffffffffu, s1[j], off);
            }
        }

        const float inv0 = 1.f / fmaxf(sqrtf(ss0), 1e-12f);
        const float inv1 = 1.f / fmaxf(sqrtf(ss1), 1e-12f);
        #pragma unroll
        for (int j = 0; j < POOL; j++) { s0[j] *= inv0; s1[j] *= inv1; }

        // dist bookkeeping: pool-sums of sim rows 0..19
        if (lane == 0) {
            if (r0 < POOL) {
                float rs = 0.f;
                #pragma unroll
                for (int j = 0; j < POOL; j++) rs += s0[j];
                g_rowsum[r0] = rs;
            }
            if (r1 < POOL) {
                float rs = 0.f;
                #pragma unroll
                for (int j = 0; j < POOL; j++) rs += s1[j];
                g_rowsum[r1] = rs;
            }
        }

        // iterative top-9 (strict '>' => lower index wins ties, matches lax.top_k)
        int idx0[TOPK], idx1[TOPK];
        #pragma unroll
        for (int t = 0; t < TOPK; t++) {
            float best = -3.4e38f; int bj = 0;
            #pragma unroll
            for (int j = 0; j < POOL; j++)
                if (s0[j] > best) { best = s0[j]; bj = j; }
            idx0[t] = bj;
            #pragma unroll
            for (int j = 0; j < POOL; j++)
                if (j == bj) s0[j] = -3.4e38f;
        }
        #pragma unroll
        for (int t = 0; t < TOPK; t++) {
            float best = -3.4e38f; int bj = 0;
            #pragma unroll
            for (int j = 0; j < POOL; j++)
                if (s1[j] > best) { best = s1[j]; bj = j; }
            idx1[t] = bj;
            #pragma unroll
            for (int j = 0; j < POOL; j++)
                if (j == bj) s1[j] = -3.4e38f;
        }

        if (lane == 0) {
            #pragma unroll
            for (int t = 0; t < TOPK; t++) {
                atomicAdd(&s_count[idx0[t]], 1u);
                atomicAdd(&s_count[idx1[t]], 1u);
            }
        }

        // gather: 18 prompt-row copies, coalesced streaming stores
        const float4* __restrict__ pbase =
            (const float4*)(prompts + (size_t)(*layer) * POOL * DIM);
        float4* __restrict__ o0 = (float4*)out + (size_t)r0 * (TOPK * DIM / 4);
        float4* __restrict__ o1 = (float4*)out + (size_t)r1 * (TOPK * DIM / 4);
        #pragma unroll
        for (int t = 0; t < TOPK; t++) {
            const float4* pr0 = pbase + idx0[t] * (DIM / 4);
            const float4* pr1 = pbase + idx1[t] * (DIM / 4);
            #pragma unroll
            for (int i = 0; i < NVEC; i++) {
                __stcs(o0 + t * (DIM / 4) + lane + 32 * i, __ldg(pr0 + lane + 32 * i));
                __stcs(o1 + t * (DIM / 4) + lane + 32 * i, __ldg(pr1 + lane + 32 * i));
            }
        }
    }

    __syncthreads();
    if (threadIdx.x < POOL)
        atomicAdd(&g_count[threadIdx.x], s_count[threadIdx.x]);
}

// ---------------------------------------------------------------------------
// finalize: dist = 1 - sum_r count[r]*rowsum[r] / (B*TOPK*POOL)
// ---------------------------------------------------------------------------
__global__ void finalize_kernel(float* __restrict__ out,
                                long long total, long long out_size, int B)
{
    double s = 0.0;
    #pragma unroll
    for (int r = 0; r < POOL; r++)
        s += (double)g_count[r] * (double)g_rowsum[r];
    const float dist = (float)(1.0 - s / ((double)B * TOPK * POOL));
    for (long long i = total + threadIdx.x; i < out_size; i += blockDim.x)
        out[i] = dist;
}

extern "C" void kernel_launch(void* const* d_in, const int* in_sizes, int n_in,
                              void* d_out, int out_size)
{
    const float* x       = (const float*)d_in[0];
    const float* keys    = (const float*)d_in[1];
    const float* prompts = (const float*)d_in[2];
    const int*   layer   = (const int*)d_in[3];

    const int B = in_sizes[0] / DIM;
    const long long total = (long long)B * TOPK * DIM;

    prep_kernel<<<1, 640>>>(keys, layer);
    pool_main<<<(B + ROWS_PER_BLOCK - 1) / ROWS_PER_BLOCK, 256>>>(
        x, prompts, layer, (float*)d_out, B);
    finalize_kernel<<<1, 32>>>((float*)d_out, total, (long long)out_size, B);
}